// round 15
// baseline (speedup 1.0000x reference)
#include <cuda_runtime.h>
#include <cuda_bf16.h>
#include <cstdint>

#define Dm 1024
#define NELEM (Dm * Dm)

// fp32 scratch
__device__ float g_Cq[NELEM];
__device__ float g_Ck[NELEM];
__device__ float g_Cv[NELEM];
__device__ float g_GhatT[16 * Dm];      // [hs][k]
__device__ float g_dpart[4][Dm * 16];   // k-chunk partials of d[rr][hs]
// bf16 hi/lo split scratch
__device__ __nv_bfloat16 g_Ah[NELEM], g_Al[NELEM];          // query
__device__ __nv_bfloat16 g_Wh[4 * NELEM], g_Wl[4 * NELEM];  // Wq,Wk,Wv,Wo
__device__ __nv_bfloat16 g_AOh[NELEM], g_AOl[NELEM];        // attention out

__device__ __forceinline__ void cp_async16(uint32_t s, const void* g) {
    asm volatile("cp.async.cg.shared.global [%0], [%1], 16;" :: "r"(s), "l"(g));
}
__device__ __forceinline__ uint32_t smem_u32(const void* p) {
    uint32_t a;
    asm("{ .reg .u64 t; cvta.to.shared.u64 t, %1; cvt.u32.u64 %0, t; }" : "=r"(a) : "l"(p));
    return a;
}
__device__ __forceinline__ void mma_bf16(float* c, uint32_t a0, uint32_t a1,
                                         uint32_t a2, uint32_t a3,
                                         uint32_t b0, uint32_t b1) {
    asm volatile(
        "mma.sync.aligned.m16n8k16.row.col.f32.bf16.bf16.f32 "
        "{%0,%1,%2,%3}, {%4,%5,%6,%7}, {%8,%9}, {%0,%1,%2,%3};"
        : "+f"(c[0]), "+f"(c[1]), "+f"(c[2]), "+f"(c[3])
        : "r"(a0), "r"(a1), "r"(a2), "r"(a3), "r"(b0), "r"(b1));
}
__device__ __forceinline__ void ldsm_x4(uint32_t* r, uint32_t addr) {
    asm volatile("ldmatrix.sync.aligned.m8n8.x4.shared.b16 {%0,%1,%2,%3}, [%4];"
                 : "=r"(r[0]), "=r"(r[1]), "=r"(r[2]), "=r"(r[3]) : "r"(addr));
}

// ---------------------------------------------------------------------------
// split5 + ghat fused. grid (1024, 6) x 256.
// ---------------------------------------------------------------------------
__global__ __launch_bounds__(256) void split_ghat(const float* __restrict__ q,
                                                  const float* __restrict__ wq,
                                                  const float* __restrict__ wk,
                                                  const float* __restrict__ wv,
                                                  const float* __restrict__ wo,
                                                  const float* __restrict__ Wr,
                                                  const float* __restrict__ spk_emb) {
    const int arr = blockIdx.y;
    if (arr == 5) {
        if (blockIdx.x >= 128) return;
        __shared__ float part[128];
        const int kc = blockIdx.x & 7;
        const int hs = blockIdx.x >> 3;
        const int kk = threadIdx.x & 127;
        const int ch = threadIdx.x >> 7;
        const float* base = Wr + (size_t)(hs * 64 + ch * 32) * 1024 + kc * 128 + kk;
        float s = 0.f;
#pragma unroll
        for (int c2 = 0; c2 < 32; c2++)
            s = fmaf(base[(size_t)c2 * 1024], spk_emb[hs * 64 + ch * 32 + c2], s);
        if (ch) part[kk] = s;
        __syncthreads();
        if (!ch) g_GhatT[hs * 1024 + kc * 128 + kk] = s + part[kk];
        return;
    }
    const float* src = (arr == 0) ? q : (arr == 1) ? wq : (arr == 2) ? wk
                                     : (arr == 3) ? wv : wo;
    __nv_bfloat16* hi = (arr == 0) ? g_Ah : g_Wh + (size_t)(arr - 1) * NELEM;
    __nv_bfloat16* lo = (arr == 0) ? g_Al : g_Wl + (size_t)(arr - 1) * NELEM;
    const int idx = (blockIdx.x * 256 + threadIdx.x) * 4;
    float4 v = *(const float4*)(src + idx);
    float f[4] = {v.x, v.y, v.z, v.w};
    unsigned short hb[4], lb[4];
#pragma unroll
    for (int i = 0; i < 4; i++) {
        __nv_bfloat16 hv = __float2bfloat16(f[i]);
        float res = f[i] - __bfloat162float(hv);
        __nv_bfloat16 lv = __float2bfloat16(res);
        hb[i] = *(unsigned short*)&hv;
        lb[i] = *(unsigned short*)&lv;
    }
    *(ushort4*)(hi + idx) = make_ushort4(hb[0], hb[1], hb[2], hb[3]);
    *(ushort4*)(lo + idx) = make_ushort4(lb[0], lb[1], lb[2], lb[3]);
}

// ---------------------------------------------------------------------------
// bf16x3 GEMM core with warp split-K: BM=64, BN=64, BK=32, 256 threads
// (8 warps, 2x2 m/n grid x 2 k-halves). Double-buffered cp.async + ldmatrix.
// Warps 4-7 accumulate k-half 1; reduced through smem at the end.
// ---------------------------------------------------------------------------
#define RPAD 40
#define A_T (64 * RPAD)
#define B_T (64 * RPAD)
#define OF_AH0 0
#define OF_AH1 A_T
#define OF_AL0 (2 * A_T)
#define OF_AL1 (3 * A_T)
#define OF_BH0 (4 * A_T)
#define OF_BH1 (4 * A_T + B_T)
#define OF_BL0 (4 * A_T + 2 * B_T)
#define OF_BL1 (4 * A_T + 3 * B_T)
#define GEMM_SMEM_BYTES ((4 * A_T + 4 * B_T) * 2)   // 40960

__device__ __forceinline__ void gemm_core(const __nv_bfloat16* __restrict__ Ah,
                                          const __nv_bfloat16* __restrict__ Al,
                                          const __nv_bfloat16* __restrict__ Bh,
                                          const __nv_bfloat16* __restrict__ Bl,
                                          float* __restrict__ C,
                                          const float* __restrict__ bias,
                                          int m0, int n0) {
    extern __shared__ __nv_bfloat16 smb[];
    const uint32_t sb = smem_u32(smb);
    const int tid = threadIdx.x;
    const int wid = tid >> 5, lane = tid & 31;
    const int g = lane >> 2, tg = lane & 3;
    const int khalf = wid >> 2;            // 0 or 1: which 16-k half
    const int wq = wid & 3;
    const int wm = wq >> 1, wn = wq & 1;   // 2x2 m/n grid

    const int lane7 = lane & 7;
    const uint32_t aRow = (uint32_t)(wm * 32 + ((lane >> 3) & 1) * 8 + lane7);
    const uint32_t aK4 = (uint32_t)((lane >> 4) * 4);
    const uint32_t bRow = (uint32_t)(wn * 32 + (lane >> 4) * 8 + lane7);
    const uint32_t bK4 = (uint32_t)(((lane >> 3) & 1) * 4);
    const uint32_t kw = (uint32_t)(khalf * 8);   // word offset of my k-half

    float acc[2][4][4];
#pragma unroll
    for (int mt = 0; mt < 2; mt++)
#pragma unroll
        for (int nt = 0; nt < 4; nt++)
#pragma unroll
            for (int r = 0; r < 4; r++) acc[mt][nt][r] = 0.f;

    // 256 threads: one 16B chunk per thread per tile
    const int lrow = tid >> 2, lc16 = tid & 3;
    auto load_tiles = [&](int buf, int k0) {
        const uint32_t ah = sb + (buf ? OF_AH1 : OF_AH0) * 2;
        const uint32_t al = sb + (buf ? OF_AL1 : OF_AL0) * 2;
        const uint32_t bh = sb + (buf ? OF_BH1 : OF_BH0) * 2;
        const uint32_t bl = sb + (buf ? OF_BL1 : OF_BL0) * 2;
        uint32_t off = (uint32_t)(lrow * RPAD + lc16 * 8) * 2;
        const size_t gsrc = (size_t)lrow * 1024 + k0 + lc16 * 8;
        cp_async16(ah + off, Ah + (size_t)m0 * 1024 + gsrc);
        cp_async16(al + off, Al + (size_t)m0 * 1024 + gsrc);
        cp_async16(bh + off, Bh + (size_t)n0 * 1024 + gsrc);
        cp_async16(bl + off, Bl + (size_t)n0 * 1024 + gsrc);
        asm volatile("cp.async.commit_group;");
    };

    load_tiles(0, 0);

    for (int it = 0; it < 32; ++it) {
        const int cur = it & 1;
        if (it + 1 < 32) {
            load_tiles(cur ^ 1, (it + 1) * 32);
            asm volatile("cp.async.wait_group 1;");
        } else {
            asm volatile("cp.async.wait_group 0;");
        }
        __syncthreads();

        const uint32_t bAH = sb + (cur ? OF_AH1 : OF_AH0) * 2;
        const uint32_t bAL = sb + (cur ? OF_AL1 : OF_AL0) * 2;
        const uint32_t bBH = sb + (cur ? OF_BH1 : OF_BH0) * 2;
        const uint32_t bBL = sb + (cur ? OF_BL1 : OF_BL0) * 2;

        uint32_t ah4[2][4], al4[2][4];
        uint32_t bh4[2][4], bl4[2][4];
#pragma unroll
        for (int mt = 0; mt < 2; mt++) {
            const uint32_t aoff = ((aRow + (uint32_t)(mt * 16)) * 20 + kw + aK4) * 4;
            ldsm_x4(ah4[mt], bAH + aoff);
            ldsm_x4(al4[mt], bAL + aoff);
        }
#pragma unroll
        for (int p = 0; p < 2; p++) {
            const uint32_t boff = ((bRow + (uint32_t)(p * 16)) * 20 + kw + bK4) * 4;
            ldsm_x4(bh4[p], bBH + boff);
            ldsm_x4(bl4[p], bBL + boff);
        }
#pragma unroll
        for (int p = 0; p < 2; p++)
#pragma unroll
            for (int mt = 0; mt < 2; mt++) {
                mma_bf16(acc[mt][2 * p], ah4[mt][0], ah4[mt][1], ah4[mt][2],
                         ah4[mt][3], bh4[p][0], bh4[p][1]);
                mma_bf16(acc[mt][2 * p + 1], ah4[mt][0], ah4[mt][1], ah4[mt][2],
                         ah4[mt][3], bh4[p][2], bh4[p][3]);
            }
#pragma unroll
        for (int p = 0; p < 2; p++)
#pragma unroll
            for (int mt = 0; mt < 2; mt++) {
                mma_bf16(acc[mt][2 * p], ah4[mt][0], ah4[mt][1], ah4[mt][2],
                         ah4[mt][3], bl4[p][0], bl4[p][1]);
                mma_bf16(acc[mt][2 * p + 1], ah4[mt][0], ah4[mt][1], ah4[mt][2],
                         ah4[mt][3], bl4[p][2], bl4[p][3]);
            }
#pragma unroll
        for (int p = 0; p < 2; p++)
#pragma unroll
            for (int mt = 0; mt < 2; mt++) {
                mma_bf16(acc[mt][2 * p], al4[mt][0], al4[mt][1], al4[mt][2],
                         al4[mt][3], bh4[p][0], bh4[p][1]);
                mma_bf16(acc[mt][2 * p + 1], al4[mt][0], al4[mt][1], al4[mt][2],
                         al4[mt][3], bh4[p][2], bh4[p][3]);
            }
        __syncthreads();
    }

    // ---- reduce k-half 1 into k-half 0 via smem (reuses tile smem) ----
    float* red = (float*)smb;          // 128 threads x 32 floats = 16KB <= 40KB
    if (khalf == 1) {
        const int t = (wq << 5) | lane;   // 0..127
#pragma unroll
        for (int mt = 0; mt < 2; mt++)
#pragma unroll
            for (int nt = 0; nt < 4; nt++)
#pragma unroll
                for (int r = 0; r < 4; r++)
                    red[(((mt * 4 + nt) * 4 + r) << 7) | t] = acc[mt][nt][r];
    }
    __syncthreads();
    if (khalf == 1) return;
    {
        const int t = (wq << 5) | lane;
#pragma unroll
        for (int mt = 0; mt < 2; mt++)
#pragma unroll
            for (int nt = 0; nt < 4; nt++)
#pragma unroll
                for (int r = 0; r < 4; r++)
                    acc[mt][nt][r] += red[(((mt * 4 + nt) * 4 + r) << 7) | t];
    }

#pragma unroll
    for (int mt = 0; mt < 2; mt++) {
        const int r0 = m0 + wm * 32 + mt * 16 + g;
#pragma unroll
        for (int nt = 0; nt < 4; nt++) {
            const int col = n0 + wn * 32 + nt * 8 + tg * 2;
            float bx = 0.f, by = 0.f;
            if (bias) {
                bx = bias[col];
                by = bias[col + 1];
            }
            float2 v0 = make_float2(acc[mt][nt][0] + bx, acc[mt][nt][1] + by);
            float2 v1 = make_float2(acc[mt][nt][2] + bx, acc[mt][nt][3] + by);
            *(float2*)(C + (size_t)r0 * 1024 + col) = v0;
            *(float2*)(C + (size_t)(r0 + 8) * 1024 + col) = v1;
        }
    }
}

// ---------------------------------------------------------------------------
// Fused mid kernel, grid (16, 16, 4) x 256.
// ---------------------------------------------------------------------------
__global__ __launch_bounds__(256) void gemm_mid(const float* __restrict__ spk_emb,
                                                const float* __restrict__ relpe) {
    const int z = blockIdx.z;
    if (z < 3) {
        const __nv_bfloat16* Bh = g_Wh + (size_t)z * NELEM;
        const __nv_bfloat16* Bl = g_Wl + (size_t)z * NELEM;
        float* C = (z == 0) ? g_Cq : (z == 1) ? g_Ck : g_Cv;
        const float* bias = (z == 0) ? spk_emb : nullptr;
        gemm_core(g_Ah, g_Al, Bh, Bl, C, bias, blockIdx.y * 64, blockIdx.x * 64);
        return;
    }
    // dmat: 256 logical blocks x 256 threads, one (rr, hs) per thread
    const int f = blockIdx.y * 16 + blockIdx.x;
    const int chunk = f & 3;
    const int rr = (f >> 2) * 16 + (threadIdx.x >> 4);
    const int hs = threadIdx.x & 15;
    const int k0 = chunk * 256;
    const float4* arow = (const float4*)(relpe + (size_t)rr * 1024 + k0);
    const float4* grow = (const float4*)(g_GhatT + (size_t)hs * 1024 + k0);
    float a0 = 0.f, a1 = 0.f, a2 = 0.f, a3 = 0.f;
#pragma unroll 8
    for (int k4 = 0; k4 < 64; k4++) {
        float4 gv = grow[k4];
        float4 x = arow[k4];
        a0 = fmaf(x.x, gv.x, a0);
        a1 = fmaf(x.y, gv.y, a1);
        a2 = fmaf(x.z, gv.z, a2);
        a3 = fmaf(x.w, gv.w, a3);
    }
    g_dpart[chunk][rr * 16 + hs] = (a0 + a1) + (a2 + a3);
}

__global__ __launch_bounds__(256) void gemm_out(float* __restrict__ out) {
    gemm_core(g_AOh, g_AOl, g_Wh + (size_t)3 * NELEM, g_Wl + (size_t)3 * NELEM,
              out, nullptr, blockIdx.y * 64, blockIdx.x * 64);
}

// ---------------------------------------------------------------------------
// Fused attention per (b, h) — round-12 proven version (FFMA + warp softmax).
// ---------------------------------------------------------------------------
#define QS_OFF 0
#define KS_OFF 8320
#define VS_OFF 16640
#define S_OFF 24960
#define E0_OFF 41472
#define E1_OFF 41536
#define CV_OFF 41600
#define SD0_OFF 41728
#define SD1_OFF 41856
#define ATTN_SMEM_FLOATS 41984
#define ATTN_SMEM_BYTES (ATTN_SMEM_FLOATS * 4)

__global__ __launch_bounds__(256) void attn_kernel(const int* __restrict__ spk_mask,
                                                   const float* __restrict__ spk_emb) {
    extern __shared__ float sm[];
    float* Qs = sm + QS_OFF;
    float* Ks = sm + KS_OFF;
    float* Vs = sm + VS_OFF;
    float* S = sm + S_OFF;
    float* e0h = sm + E0_OFF;
    float* e1h = sm + E1_OFF;
    float* cvec = sm + CV_OFF;
    float* sd0 = sm + SD0_OFF;
    float* sd1 = sm + SD1_OFF;

    const int b = blockIdx.x, h = blockIdx.y;
    const int tid = threadIdx.x;

    for (int idx = tid; idx < 128 * 64; idx += 256) {
        int i = idx >> 6, hd = idx & 63;
        size_t g = (size_t)(i * 8 + b) * 1024 + h * 64 + hd;
        Qs[i * 65 + hd] = g_Cq[g];
        Ks[i * 65 + hd] = g_Ck[g];
        Vs[i * 65 + hd] = g_Cv[g];
    }
    if (tid < 64) {
        e0h[tid] = spk_emb[h * 64 + tid];
        e1h[tid] = spk_emb[1024 + h * 64 + tid];
    } else if (tid < 192) {
        int j = tid - 64;
        int off = (j * 8 + b) * 16 + h;
        cvec[j] = (g_dpart[0][off] + g_dpart[1][off]) +
                  (g_dpart[2][off] + g_dpart[3][off]);
    }
    __syncthreads();

    if (tid < 128) {
        float s0 = 0.f, s1 = 0.f;
        const float* qrow = Qs + tid * 65;
#pragma unroll
        for (int k = 0; k < 64; k++) {
            float q = qrow[k];
            s0 = fmaf(q, e0h[k], s0);
            s1 = fmaf(q, e1h[k], s1);
        }
        sd0[tid] = s0;
        sd1[tid] = s1;
    }
    __syncthreads();

    const int ti = tid >> 4, tj = tid & 15;
    float acc[8][8];
#pragma unroll
    for (int a = 0; a < 8; a++)
#pragma unroll
        for (int c2 = 0; c2 < 8; c2++) acc[a][c2] = 0.f;
    for (int k = 0; k < 64; k++) {
        float qa[8], kb[8];
#pragma unroll
        for (int ii = 0; ii < 8; ii++) qa[ii] = Qs[(ti + 16 * ii) * 65 + k];
#pragma unroll
        for (int jj = 0; jj < 8; jj++) kb[jj] = Ks[(tj + 16 * jj) * 65 + k];
#pragma unroll
        for (int ii = 0; ii < 8; ii++)
#pragma unroll
            for (int jj = 0; jj < 8; jj++)
                acc[ii][jj] = fmaf(qa[ii], kb[jj], acc[ii][jj]);
    }
    const int* spm = spk_mask + b * 128 * 128;
#pragma unroll
    for (int ii = 0; ii < 8; ii++) {
        int i = ti + 16 * ii;
#pragma unroll
        for (int jj = 0; jj < 8; jj++) {
            int j = tj + 16 * jj;
            float v;
            if (j <= i) {
                float a2 = spm[i * 128 + j] ? sd1[i] : sd0[i];
                float a3 = cvec[127 - i + j];
                v = (acc[ii][jj] + a2 + a3) * 0.125f;
            } else {
                v = 1e-30f;
            }
            S[i * 129 + j] = v;
        }
    }
    __syncthreads();

    // softmax: warp-per-row with shuffle reductions (8 warps x 16 rows)
    {
        const int lane = tid & 31, w = tid >> 5;
#pragma unroll
        for (int rloc = 0; rloc < 16; rloc++) {
            float* row = S + (w * 16 + rloc) * 129;
            float x0 = row[lane], x1 = row[lane + 32];
            float x2 = row[lane + 64], x3 = row[lane + 96];
            float mx = fmaxf(fmaxf(x0, x1), fmaxf(x2, x3));
#pragma unroll
            for (int o = 16; o > 0; o >>= 1)
                mx = fmaxf(mx, __shfl_xor_sync(0xffffffffu, mx, o));
            float e0 = __expf(x0 - mx), e1 = __expf(x1 - mx);
            float e2 = __expf(x2 - mx), e3 = __expf(x3 - mx);
            float sum = (e0 + e1) + (e2 + e3);
#pragma unroll
            for (int o = 16; o > 0; o >>= 1)
                sum += __shfl_xor_sync(0xffffffffu, sum, o);
            float inv = 1.f / sum;
            row[lane] = e0 * inv;
            row[lane + 32] = e1 * inv;
            row[lane + 64] = e2 * inv;
            row[lane + 96] = e3 * inv;
        }
    }
    __syncthreads();

    const int r = tid >> 3, c = tid & 7;
    float oacc[4][8];
#pragma unroll
    for (int a = 0; a < 4; a++)
#pragma unroll
        for (int c2 = 0; c2 < 8; c2++) oacc[a][c2] = 0.f;
    for (int j = 0; j < 128; j++) {
        float wv[4], vv[8];
#pragma unroll
        for (int ii = 0; ii < 4; ii++) wv[ii] = S[(r + 32 * ii) * 129 + j];
#pragma unroll
        for (int jj = 0; jj < 8; jj++) vv[jj] = Vs[j * 65 + c + 8 * jj];
#pragma unroll
        for (int ii = 0; ii < 4; ii++)
#pragma unroll
            for (int jj = 0; jj < 8; jj++)
                oacc[ii][jj] = fmaf(wv[ii], vv[jj], oacc[ii][jj]);
    }
#pragma unroll
    for (int ii = 0; ii < 4; ii++) {
        int i = r + 32 * ii;
#pragma unroll
        for (int jj = 0; jj < 8; jj++) {
            int hd = c + 8 * jj;
            size_t g = (size_t)(i * 8 + b) * 1024 + h * 64 + hd;
            float v = oacc[ii][jj];
            __nv_bfloat16 hb = __float2bfloat16(v);
            float res = v - __bfloat162float(hb);
            g_AOh[g] = hb;
            g_AOl[g] = __float2bfloat16(res);
        }
    }
}

// ---------------------------------------------------------------------------
extern "C" void kernel_launch(void* const* d_in, const int* in_sizes, int n_in,
                              void* d_out, int out_size) {
    const float* query = (const float*)d_in[0];
    const float* rel_pe = (const float*)d_in[1];
    const float* Wq = (const float*)d_in[3];
    const float* Wk = (const float*)d_in[4];
    const float* Wv = (const float*)d_in[5];
    const float* Wr = (const float*)d_in[6];
    const float* Wo = (const float*)d_in[7];
    const float* spk_emb = (const float*)d_in[8];
    const int* spk_mask = (const int*)d_in[10];
    float* out = (float*)d_out;

    cudaFuncSetAttribute(attn_kernel, cudaFuncAttributeMaxDynamicSharedMemorySize,
                         ATTN_SMEM_BYTES);
    cudaFuncSetAttribute(gemm_mid, cudaFuncAttributeMaxDynamicSharedMemorySize,
                         GEMM_SMEM_BYTES);
    cudaFuncSetAttribute(gemm_out, cudaFuncAttributeMaxDynamicSharedMemorySize,
                         GEMM_SMEM_BYTES);

    split_ghat<<<dim3(1024, 6), 256>>>(query, Wq, Wk, Wv, Wo, Wr, spk_emb);
    gemm_mid<<<dim3(16, 16, 4), 256, GEMM_SMEM_BYTES>>>(spk_emb, rel_pe);
    attn_kernel<<<dim3(8, 16), 256, ATTN_SMEM_BYTES>>>(spk_mask, spk_emb);
    gemm_out<<<dim3(16, 16), 256, GEMM_SMEM_BYTES>>>(out);
}

// round 16
// speedup vs baseline: 1.0875x; 1.0875x over previous
#include <cuda_runtime.h>
#include <cuda_bf16.h>
#include <cstdint>

#define Dm 1024
#define NELEM (Dm * Dm)

// fp32 scratch
__device__ float g_Cq[NELEM];
__device__ float g_Ck[NELEM];
__device__ float g_Cv[NELEM];
__device__ float g_GhatT[16 * Dm];      // [hs][k]
__device__ float g_dpart[4][Dm * 16];   // k-chunk partials of d[rr][hs]
// bf16 hi/lo split scratch
__device__ __nv_bfloat16 g_Ah[NELEM], g_Al[NELEM];          // query
__device__ __nv_bfloat16 g_Wh[4 * NELEM], g_Wl[4 * NELEM];  // Wq,Wk,Wv,Wo
__device__ __nv_bfloat16 g_AOh[NELEM], g_AOl[NELEM];        // attention out

__device__ __forceinline__ void cp_async16(uint32_t s, const void* g) {
    asm volatile("cp.async.cg.shared.global [%0], [%1], 16;" :: "r"(s), "l"(g));
}
__device__ __forceinline__ uint32_t smem_u32(const void* p) {
    uint32_t a;
    asm("{ .reg .u64 t; cvta.to.shared.u64 t, %1; cvt.u32.u64 %0, t; }" : "=r"(a) : "l"(p));
    return a;
}
__device__ __forceinline__ void mma_bf16(float* c, uint32_t a0, uint32_t a1,
                                         uint32_t a2, uint32_t a3,
                                         uint32_t b0, uint32_t b1) {
    asm volatile(
        "mma.sync.aligned.m16n8k16.row.col.f32.bf16.bf16.f32 "
        "{%0,%1,%2,%3}, {%4,%5,%6,%7}, {%8,%9}, {%0,%1,%2,%3};"
        : "+f"(c[0]), "+f"(c[1]), "+f"(c[2]), "+f"(c[3])
        : "r"(a0), "r"(a1), "r"(a2), "r"(a3), "r"(b0), "r"(b1));
}
__device__ __forceinline__ void ldsm_x4(uint32_t* r, uint32_t addr) {
    asm volatile("ldmatrix.sync.aligned.m8n8.x4.shared.b16 {%0,%1,%2,%3}, [%4];"
                 : "=r"(r[0]), "=r"(r[1]), "=r"(r[2]), "=r"(r[3]) : "r"(addr));
}

// ---------------------------------------------------------------------------
// split5 + ghat fused. grid (1024, 6) x 256.
// ---------------------------------------------------------------------------
__global__ __launch_bounds__(256) void split_ghat(const float* __restrict__ q,
                                                  const float* __restrict__ wq,
                                                  const float* __restrict__ wk,
                                                  const float* __restrict__ wv,
                                                  const float* __restrict__ wo,
                                                  const float* __restrict__ Wr,
                                                  const float* __restrict__ spk_emb) {
    const int arr = blockIdx.y;
    if (arr == 5) {
        if (blockIdx.x >= 128) return;
        __shared__ float part[128];
        const int kc = blockIdx.x & 7;
        const int hs = blockIdx.x >> 3;
        const int kk = threadIdx.x & 127;
        const int ch = threadIdx.x >> 7;
        const float* base = Wr + (size_t)(hs * 64 + ch * 32) * 1024 + kc * 128 + kk;
        float s = 0.f;
#pragma unroll
        for (int c2 = 0; c2 < 32; c2++)
            s = fmaf(base[(size_t)c2 * 1024], spk_emb[hs * 64 + ch * 32 + c2], s);
        if (ch) part[kk] = s;
        __syncthreads();
        if (!ch) g_GhatT[hs * 1024 + kc * 128 + kk] = s + part[kk];
        return;
    }
    const float* src = (arr == 0) ? q : (arr == 1) ? wq : (arr == 2) ? wk
                                     : (arr == 3) ? wv : wo;
    __nv_bfloat16* hi = (arr == 0) ? g_Ah : g_Wh + (size_t)(arr - 1) * NELEM;
    __nv_bfloat16* lo = (arr == 0) ? g_Al : g_Wl + (size_t)(arr - 1) * NELEM;
    const int idx = (blockIdx.x * 256 + threadIdx.x) * 4;
    float4 v = *(const float4*)(src + idx);
    float f[4] = {v.x, v.y, v.z, v.w};
    unsigned short hb[4], lb[4];
#pragma unroll
    for (int i = 0; i < 4; i++) {
        __nv_bfloat16 hv = __float2bfloat16(f[i]);
        float res = f[i] - __bfloat162float(hv);
        __nv_bfloat16 lv = __float2bfloat16(res);
        hb[i] = *(unsigned short*)&hv;
        lb[i] = *(unsigned short*)&lv;
    }
    *(ushort4*)(hi + idx) = make_ushort4(hb[0], hb[1], hb[2], hb[3]);
    *(ushort4*)(lo + idx) = make_ushort4(lb[0], lb[1], lb[2], lb[3]);
}

// ---------------------------------------------------------------------------
// bf16x3 GEMM core (round-12 config, single-barrier pipeline): BM=64, BN=64,
// BK=32, 128 threads (4 warps 2x2), ldmatrix frags, double-buffered cp.async.
// Loads issued AFTER wait+sync -> one __syncthreads per chunk suffices.
// ---------------------------------------------------------------------------
#define RPAD 40
#define A_T (64 * RPAD)
#define B_T (64 * RPAD)
#define OF_AH0 0
#define OF_AH1 A_T
#define OF_AL0 (2 * A_T)
#define OF_AL1 (3 * A_T)
#define OF_BH0 (4 * A_T)
#define OF_BH1 (4 * A_T + B_T)
#define OF_BL0 (4 * A_T + 2 * B_T)
#define OF_BL1 (4 * A_T + 3 * B_T)
#define GEMM_SMEM_BYTES ((4 * A_T + 4 * B_T) * 2)   // 40960

__device__ __forceinline__ void gemm_core(const __nv_bfloat16* __restrict__ Ah,
                                          const __nv_bfloat16* __restrict__ Al,
                                          const __nv_bfloat16* __restrict__ Bh,
                                          const __nv_bfloat16* __restrict__ Bl,
                                          float* __restrict__ C,
                                          const float* __restrict__ bias,
                                          int m0, int n0) {
    extern __shared__ __nv_bfloat16 smb[];
    const uint32_t sb = smem_u32(smb);
    const int tid = threadIdx.x;
    const int wid = tid >> 5, lane = tid & 31;
    const int g = lane >> 2, tg = lane & 3;
    const int wm = wid >> 1, wn = wid & 1;

    const int lane7 = lane & 7;
    const uint32_t aRow = (uint32_t)(wm * 32 + ((lane >> 3) & 1) * 8 + lane7);
    const uint32_t aK4 = (uint32_t)((lane >> 4) * 4);
    const uint32_t bRow = (uint32_t)(wn * 32 + (lane >> 4) * 8 + lane7);
    const uint32_t bK4 = (uint32_t)(((lane >> 3) & 1) * 4);

    float acc[2][4][4];
#pragma unroll
    for (int mt = 0; mt < 2; mt++)
#pragma unroll
        for (int nt = 0; nt < 4; nt++)
#pragma unroll
            for (int r = 0; r < 4; r++) acc[mt][nt][r] = 0.f;

    auto load_tiles = [&](int buf, int k0) {
        const uint32_t ah = sb + (buf ? OF_AH1 : OF_AH0) * 2;
        const uint32_t al = sb + (buf ? OF_AL1 : OF_AL0) * 2;
        const uint32_t bh = sb + (buf ? OF_BH1 : OF_BH0) * 2;
        const uint32_t bl = sb + (buf ? OF_BL1 : OF_BL0) * 2;
#pragma unroll
        for (int i = 0; i < 2; i++) {
            int qd = tid + i * 128;
            int row = qd >> 2, c16 = qd & 3;
            uint32_t off = (uint32_t)(row * RPAD + c16 * 8) * 2;
            const size_t gsrc = (size_t)row * 1024 + k0 + c16 * 8;
            cp_async16(ah + off, Ah + (size_t)m0 * 1024 + gsrc);
            cp_async16(al + off, Al + (size_t)m0 * 1024 + gsrc);
            cp_async16(bh + off, Bh + (size_t)n0 * 1024 + gsrc);
            cp_async16(bl + off, Bl + (size_t)n0 * 1024 + gsrc);
        }
        asm volatile("cp.async.commit_group;");
    };

    load_tiles(0, 0);

    for (int it = 0; it < 32; ++it) {
        const int cur = it & 1;
        asm volatile("cp.async.wait_group 0;");
        __syncthreads();   // publishes chunk it AND proves chunk it-1 consumed
        if (it + 1 < 32) load_tiles(cur ^ 1, (it + 1) * 32);

        const uint32_t bAH = sb + (cur ? OF_AH1 : OF_AH0) * 2;
        const uint32_t bAL = sb + (cur ? OF_AL1 : OF_AL0) * 2;
        const uint32_t bBH = sb + (cur ? OF_BH1 : OF_BH0) * 2;
        const uint32_t bBL = sb + (cur ? OF_BL1 : OF_BL0) * 2;
#pragma unroll
        for (int kk = 0; kk < 2; kk++) {
            const uint32_t kw = (uint32_t)(kk * 8);
            uint32_t ah4[2][4], al4[2][4];
            uint32_t bh4[2][4], bl4[2][4];
#pragma unroll
            for (int mt = 0; mt < 2; mt++) {
                const uint32_t aoff = ((aRow + (uint32_t)(mt * 16)) * 20 + kw + aK4) * 4;
                ldsm_x4(ah4[mt], bAH + aoff);
                ldsm_x4(al4[mt], bAL + aoff);
            }
#pragma unroll
            for (int p = 0; p < 2; p++) {
                const uint32_t boff = ((bRow + (uint32_t)(p * 16)) * 20 + kw + bK4) * 4;
                ldsm_x4(bh4[p], bBH + boff);
                ldsm_x4(bl4[p], bBL + boff);
            }
#pragma unroll
            for (int p = 0; p < 2; p++)
#pragma unroll
                for (int mt = 0; mt < 2; mt++) {
                    mma_bf16(acc[mt][2 * p], ah4[mt][0], ah4[mt][1], ah4[mt][2],
                             ah4[mt][3], bh4[p][0], bh4[p][1]);
                    mma_bf16(acc[mt][2 * p + 1], ah4[mt][0], ah4[mt][1], ah4[mt][2],
                             ah4[mt][3], bh4[p][2], bh4[p][3]);
                }
#pragma unroll
            for (int p = 0; p < 2; p++)
#pragma unroll
                for (int mt = 0; mt < 2; mt++) {
                    mma_bf16(acc[mt][2 * p], ah4[mt][0], ah4[mt][1], ah4[mt][2],
                             ah4[mt][3], bl4[p][0], bl4[p][1]);
                    mma_bf16(acc[mt][2 * p + 1], ah4[mt][0], ah4[mt][1], ah4[mt][2],
                             ah4[mt][3], bl4[p][2], bl4[p][3]);
                }
#pragma unroll
            for (int p = 0; p < 2; p++)
#pragma unroll
                for (int mt = 0; mt < 2; mt++) {
                    mma_bf16(acc[mt][2 * p], al4[mt][0], al4[mt][1], al4[mt][2],
                             al4[mt][3], bh4[p][0], bh4[p][1]);
                    mma_bf16(acc[mt][2 * p + 1], al4[mt][0], al4[mt][1], al4[mt][2],
                             al4[mt][3], bh4[p][2], bh4[p][3]);
                }
        }
    }

#pragma unroll
    for (int mt = 0; mt < 2; mt++) {
        const int r0 = m0 + wm * 32 + mt * 16 + g;
#pragma unroll
        for (int nt = 0; nt < 4; nt++) {
            const int col = n0 + wn * 32 + nt * 8 + tg * 2;
            float bx = 0.f, by = 0.f;
            if (bias) {
                bx = bias[col];
                by = bias[col + 1];
            }
            float2 v0 = make_float2(acc[mt][nt][0] + bx, acc[mt][nt][1] + by);
            float2 v1 = make_float2(acc[mt][nt][2] + bx, acc[mt][nt][3] + by);
            *(float2*)(C + (size_t)r0 * 1024 + col) = v0;
            *(float2*)(C + (size_t)(r0 + 8) * 1024 + col) = v1;
        }
    }
}

// ---------------------------------------------------------------------------
// Fused mid kernel, grid (16, 16, 4) x 128.
// ---------------------------------------------------------------------------
__global__ __launch_bounds__(128) void gemm_mid(const float* __restrict__ spk_emb,
                                                const float* __restrict__ relpe) {
    const int z = blockIdx.z;
    if (z < 3) {
        const __nv_bfloat16* Bh = g_Wh + (size_t)z * NELEM;
        const __nv_bfloat16* Bl = g_Wl + (size_t)z * NELEM;
        float* C = (z == 0) ? g_Cq : (z == 1) ? g_Ck : g_Cv;
        const float* bias = (z == 0) ? spk_emb : nullptr;
        gemm_core(g_Ah, g_Al, Bh, Bl, C, bias, blockIdx.y * 64, blockIdx.x * 64);
        return;
    }
    const int f = blockIdx.y * 16 + blockIdx.x;
    const int chunk = f & 3;
    const int rrbase = (f >> 2) * 16;
    const int hs = threadIdx.x & 15;
    const int rr0 = rrbase + (threadIdx.x >> 4);
    const int k0 = chunk * 256;
    const float4* arow0 = (const float4*)(relpe + (size_t)rr0 * 1024 + k0);
    const float4* arow1 = (const float4*)(relpe + (size_t)(rr0 + 8) * 1024 + k0);
    const float4* grow = (const float4*)(g_GhatT + (size_t)hs * 1024 + k0);
    float a0 = 0.f, a1 = 0.f, b0 = 0.f, b1 = 0.f;
#pragma unroll 8
    for (int k4 = 0; k4 < 64; k4++) {
        float4 gv = grow[k4];
        float4 x = arow0[k4];
        float4 y = arow1[k4];
        a0 = fmaf(x.x, gv.x, a0);
        a1 = fmaf(x.y, gv.y, a1);
        a0 = fmaf(x.z, gv.z, a0);
        a1 = fmaf(x.w, gv.w, a1);
        b0 = fmaf(y.x, gv.x, b0);
        b1 = fmaf(y.y, gv.y, b1);
        b0 = fmaf(y.z, gv.z, b0);
        b1 = fmaf(y.w, gv.w, b1);
    }
    g_dpart[chunk][rr0 * 16 + hs] = a0 + a1;
    g_dpart[chunk][(rr0 + 8) * 16 + hs] = b0 + b1;
}

__global__ __launch_bounds__(128) void gemm_out(float* __restrict__ out) {
    gemm_core(g_AOh, g_AOl, g_Wh + (size_t)3 * NELEM, g_Wl + (size_t)3 * NELEM,
              out, nullptr, blockIdx.y * 64, blockIdx.x * 64);
}

// ---------------------------------------------------------------------------
// Fused attention per (b, h) — round-12 proven version (FFMA + warp softmax).
// ---------------------------------------------------------------------------
#define QS_OFF 0
#define KS_OFF 8320
#define VS_OFF 16640
#define S_OFF 24960
#define E0_OFF 41472
#define E1_OFF 41536
#define CV_OFF 41600
#define SD0_OFF 41728
#define SD1_OFF 41856
#define ATTN_SMEM_FLOATS 41984
#define ATTN_SMEM_BYTES (ATTN_SMEM_FLOATS * 4)

__global__ __launch_bounds__(256) void attn_kernel(const int* __restrict__ spk_mask,
                                                   const float* __restrict__ spk_emb) {
    extern __shared__ float sm[];
    float* Qs = sm + QS_OFF;
    float* Ks = sm + KS_OFF;
    float* Vs = sm + VS_OFF;
    float* S = sm + S_OFF;
    float* e0h = sm + E0_OFF;
    float* e1h = sm + E1_OFF;
    float* cvec = sm + CV_OFF;
    float* sd0 = sm + SD0_OFF;
    float* sd1 = sm + SD1_OFF;

    const int b = blockIdx.x, h = blockIdx.y;
    const int tid = threadIdx.x;

    for (int idx = tid; idx < 128 * 64; idx += 256) {
        int i = idx >> 6, hd = idx & 63;
        size_t g = (size_t)(i * 8 + b) * 1024 + h * 64 + hd;
        Qs[i * 65 + hd] = g_Cq[g];
        Ks[i * 65 + hd] = g_Ck[g];
        Vs[i * 65 + hd] = g_Cv[g];
    }
    if (tid < 64) {
        e0h[tid] = spk_emb[h * 64 + tid];
        e1h[tid] = spk_emb[1024 + h * 64 + tid];
    } else if (tid < 192) {
        int j = tid - 64;
        int off = (j * 8 + b) * 16 + h;
        cvec[j] = (g_dpart[0][off] + g_dpart[1][off]) +
                  (g_dpart[2][off] + g_dpart[3][off]);
    }
    __syncthreads();

    if (tid < 128) {
        float s0 = 0.f, s1 = 0.f;
        const float* qrow = Qs + tid * 65;
#pragma unroll
        for (int k = 0; k < 64; k++) {
            float q = qrow[k];
            s0 = fmaf(q, e0h[k], s0);
            s1 = fmaf(q, e1h[k], s1);
        }
        sd0[tid] = s0;
        sd1[tid] = s1;
    }
    __syncthreads();

    const int ti = tid >> 4, tj = tid & 15;
    float acc[8][8];
#pragma unroll
    for (int a = 0; a < 8; a++)
#pragma unroll
        for (int c2 = 0; c2 < 8; c2++) acc[a][c2] = 0.f;
    for (int k = 0; k < 64; k++) {
        float qa[8], kb[8];
#pragma unroll
        for (int ii = 0; ii < 8; ii++) qa[ii] = Qs[(ti + 16 * ii) * 65 + k];
#pragma unroll
        for (int jj = 0; jj < 8; jj++) kb[jj] = Ks[(tj + 16 * jj) * 65 + k];
#pragma unroll
        for (int ii = 0; ii < 8; ii++)
#pragma unroll
            for (int jj = 0; jj < 8; jj++)
                acc[ii][jj] = fmaf(qa[ii], kb[jj], acc[ii][jj]);
    }
    const int* spm = spk_mask + b * 128 * 128;
#pragma unroll
    for (int ii = 0; ii < 8; ii++) {
        int i = ti + 16 * ii;
#pragma unroll
        for (int jj = 0; jj < 8; jj++) {
            int j = tj + 16 * jj;
            float v;
            if (j <= i) {
                float a2 = spm[i * 128 + j] ? sd1[i] : sd0[i];
                float a3 = cvec[127 - i + j];
                v = (acc[ii][jj] + a2 + a3) * 0.125f;
            } else {
                v = 1e-30f;
            }
            S[i * 129 + j] = v;
        }
    }
    __syncthreads();

    // softmax: warp-per-row with shuffle reductions (8 warps x 16 rows)
    {
        const int lane = tid & 31, w = tid >> 5;
#pragma unroll
        for (int rloc = 0; rloc < 16; rloc++) {
            float* row = S + (w * 16 + rloc) * 129;
            float x0 = row[lane], x1 = row[lane + 32];
            float x2 = row[lane + 64], x3 = row[lane + 96];
            float mx = fmaxf(fmaxf(x0, x1), fmaxf(x2, x3));
#pragma unroll
            for (int o = 16; o > 0; o >>= 1)
                mx = fmaxf(mx, __shfl_xor_sync(0xffffffffu, mx, o));
            float e0 = __expf(x0 - mx), e1 = __expf(x1 - mx);
            float e2 = __expf(x2 - mx), e3 = __expf(x3 - mx);
            float sum = (e0 + e1) + (e2 + e3);
#pragma unroll
            for (int o = 16; o > 0; o >>= 1)
                sum += __shfl_xor_sync(0xffffffffu, sum, o);
            float inv = 1.f / sum;
            row[lane] = e0 * inv;
            row[lane + 32] = e1 * inv;
            row[lane + 64] = e2 * inv;
            row[lane + 96] = e3 * inv;
        }
    }
    __syncthreads();

    const int r = tid >> 3, c = tid & 7;
    float oacc[4][8];
#pragma unroll
    for (int a = 0; a < 4; a++)
#pragma unroll
        for (int c2 = 0; c2 < 8; c2++) oacc[a][c2] = 0.f;
    for (int j = 0; j < 128; j++) {
        float wv[4], vv[8];
#pragma unroll
        for (int ii = 0; ii < 4; ii++) wv[ii] = S[(r + 32 * ii) * 129 + j];
#pragma unroll
        for (int jj = 0; jj < 8; jj++) vv[jj] = Vs[j * 65 + c + 8 * jj];
#pragma unroll
        for (int ii = 0; ii < 4; ii++)
#pragma unroll
            for (int jj = 0; jj < 8; jj++)
                oacc[ii][jj] = fmaf(wv[ii], vv[jj], oacc[ii][jj]);
    }
#pragma unroll
    for (int ii = 0; ii < 4; ii++) {
        int i = r + 32 * ii;
#pragma unroll
        for (int jj = 0; jj < 8; jj++) {
            int hd = c + 8 * jj;
            size_t g = (size_t)(i * 8 + b) * 1024 + h * 64 + hd;
            float v = oacc[ii][jj];
            __nv_bfloat16 hb = __float2bfloat16(v);
            float res = v - __bfloat162float(hb);
            g_AOh[g] = hb;
            g_AOl[g] = __float2bfloat16(res);
        }
    }
}

// ---------------------------------------------------------------------------
extern "C" void kernel_launch(void* const* d_in, const int* in_sizes, int n_in,
                              void* d_out, int out_size) {
    const float* query = (const float*)d_in[0];
    const float* rel_pe = (const float*)d_in[1];
    const float* Wq = (const float*)d_in[3];
    const float* Wk = (const float*)d_in[4];
    const float* Wv = (const float*)d_in[5];
    const float* Wr = (const float*)d_in[6];
    const float* Wo = (const float*)d_in[7];
    const float* spk_emb = (const float*)d_in[8];
    const int* spk_mask = (const int*)d_in[10];
    float* out = (float*)d_out;

    cudaFuncSetAttribute(attn_kernel, cudaFuncAttributeMaxDynamicSharedMemorySize,
                         ATTN_SMEM_BYTES);
    cudaFuncSetAttribute(gemm_mid, cudaFuncAttributeMaxDynamicSharedMemorySize,
                         GEMM_SMEM_BYTES);
    cudaFuncSetAttribute(gemm_out, cudaFuncAttributeMaxDynamicSharedMemorySize,
                         GEMM_SMEM_BYTES);

    split_ghat<<<dim3(1024, 6), 256>>>(query, Wq, Wk, Wv, Wo, Wr, spk_emb);
    gemm_mid<<<dim3(16, 16, 4), 128, GEMM_SMEM_BYTES>>>(spk_emb, rel_pe);
    attn_kernel<<<dim3(8, 16), 256, ATTN_SMEM_BYTES>>>(spk_mask, spk_emb);
    gemm_out<<<dim3(16, 16), 128, GEMM_SMEM_BYTES>>>(out);
}